// round 6
// baseline (speedup 1.0000x reference)
#include <cuda_runtime.h>
#include <cuda_fp16.h>

// ---------------------------------------------------------------------------
// Mipmapped texture sampling, GB300 — fp16 pyramid (32B/texel, HWC).
// Level i (i>=1) texel = 0.25 * 2x2 of base at y0 = y*2^i + 2^(i-1) - 1
// (exact algebra of align_corners=False bilinear downsample by 2^i).
// NO addressable local state escapes to memory: arrays only with
// fully-unrolled constant indices, scalar bitcasts only.
// ---------------------------------------------------------------------------

#define NLEV 8

__device__ __align__(16) __half g_pyr[5592320];

__constant__ int c_off[NLEV] = {
    0, 4194304, 5242880, 5505024, 5570560, 5586944, 5591040, 5592064
};

__device__ __forceinline__ float2 u2f2(unsigned u) {
    return __half22float2(*reinterpret_cast<const __half2*>(&u));
}
__device__ __forceinline__ unsigned f2u(float a, float b) {
    __half2 h = __floats2half2_rn(a, b);
    return *reinterpret_cast<const unsigned*>(&h);
}
__device__ __forceinline__ float f4get(const float4& v, int j) {
    // j is compile-time constant after full unroll
    return j == 0 ? v.x : (j == 1 ? v.y : (j == 2 ? v.z : v.w));
}

// ---------------------------------------------------------------------------
// Kernel 1: CHW (16,512,512) fp32 -> HWC fp16 level 0.
// One thread per 4 pixels: 16 x LDG.128 (one per plane, MLP=16),
// 8 x STG.128 contiguous (4 texels x 32B = 128B per thread).
// ---------------------------------------------------------------------------
__global__ void k_transpose(const float* __restrict__ tex) {
    int tid = blockIdx.x * blockDim.x + threadIdx.x;   // 65536 threads
    if (tid >= 65536) return;
    const int plane4 = 512 * 512 / 4;

    float4 v[16];
#pragma unroll
    for (int c = 0; c < 16; c++)
        v[c] = __ldg(reinterpret_cast<const float4*>(tex) + c * plane4 + tid);

    uint4* dst = reinterpret_cast<uint4*>(g_pyr) + tid * 8;  // 4 texels * 2 uint4
#pragma unroll
    for (int j = 0; j < 4; j++) {
        uint4 a, b;
        a.x = f2u(f4get(v[0],  j), f4get(v[1],  j));
        a.y = f2u(f4get(v[2],  j), f4get(v[3],  j));
        a.z = f2u(f4get(v[4],  j), f4get(v[5],  j));
        a.w = f2u(f4get(v[6],  j), f4get(v[7],  j));
        b.x = f2u(f4get(v[8],  j), f4get(v[9],  j));
        b.y = f2u(f4get(v[10], j), f4get(v[11], j));
        b.z = f2u(f4get(v[12], j), f4get(v[13], j));
        b.w = f2u(f4get(v[14], j), f4get(v[15], j));
        dst[2 * j]     = a;
        dst[2 * j + 1] = b;
    }
}

// ---------------------------------------------------------------------------
// Kernel 2: levels 1..7 as direct 2x2 average of level 0.
// 2 threads per destination texel (8 channels each), register accumulators.
// ---------------------------------------------------------------------------
__global__ void k_mips() {
    int idx = blockIdx.x * blockDim.x + threadIdx.x;
    if (idx >= 2 * 87376) return;
    int t   = idx & 1;
    int rem = idx >> 1;

    int l = 1;
#pragma unroll
    for (int i = 1; i < NLEV; i++) {
        int np = (512 >> i) * (512 >> i);
        if (rem < np) { l = i; break; }
        rem -= np;
    }
    int s  = 512 >> l;
    int x  = rem & (s - 1);
    int y  = rem >> (9 - l);
    int sc = 1 << l;
    int x0 = x * sc + (sc >> 1) - 1;
    int y0 = y * sc + (sc >> 1) - 1;

    const uint4* base = reinterpret_cast<const uint4*>(g_pyr);
    uint4 va = __ldg(&base[(y0       * 512 + x0    ) * 2 + t]);
    uint4 vb = __ldg(&base[(y0       * 512 + x0 + 1) * 2 + t]);
    uint4 vc = __ldg(&base[((y0 + 1) * 512 + x0    ) * 2 + t]);
    uint4 vd = __ldg(&base[((y0 + 1) * 512 + x0 + 1) * 2 + t]);

    float4 A = make_float4(0.f, 0.f, 0.f, 0.f);
    float4 B = make_float4(0.f, 0.f, 0.f, 0.f);
#define ACC(V) {                                               \
        float2 f0 = u2f2(V.x); A.x += f0.x; A.y += f0.y;        \
        float2 f1 = u2f2(V.y); A.z += f1.x; A.w += f1.y;        \
        float2 f2 = u2f2(V.z); B.x += f2.x; B.y += f2.y;        \
        float2 f3 = u2f2(V.w); B.z += f3.x; B.w += f3.y; }
    ACC(va) ACC(vb) ACC(vc) ACC(vd)
#undef ACC

    uint4 r;
    r.x = f2u(0.25f * A.x, 0.25f * A.y);
    r.y = f2u(0.25f * A.z, 0.25f * A.w);
    r.z = f2u(0.25f * B.x, 0.25f * B.y);
    r.w = f2u(0.25f * B.z, 0.25f * B.w);
    reinterpret_cast<uint4*>(g_pyr + c_off[l])[(y * s + x) * 2 + t] = r;
}

// ---------------------------------------------------------------------------
// Kernel 3: sample. 2 threads/query, 8 channels each (one LDG.128 per texel).
// All 8 loads (both levels) issued before any accumulation (MLP=8).
// ---------------------------------------------------------------------------
__device__ __forceinline__ void lvl_setup(int l, float gx, float gy, int t, float lw,
        const uint4*& p00, const uint4*& p01, const uint4*& p10, const uint4*& p11,
        float& w00, float& w01, float& w10, float& w11) {
    int   s  = 512 >> l;
    float fs = (float)(s - 1);
    float x = fminf(fmaxf((gx + 1.0f) * 0.5f * fs, 0.0f), fs);
    float y = fminf(fmaxf((gy + 1.0f) * 0.5f * fs, 0.0f), fs);
    int x0 = (int)x;
    int y0 = (int)y;
    int x1 = min(x0 + 1, s - 1);
    int y1 = min(y0 + 1, s - 1);
    float fx = x - (float)x0;
    float fy = y - (float)y0;

    const uint4* b = reinterpret_cast<const uint4*>(g_pyr + c_off[l]);
    int r0 = y0 * s, r1 = y1 * s;
    p00 = &b[(r0 + x0) * 2 + t];
    p01 = &b[(r0 + x1) * 2 + t];
    p10 = &b[(r1 + x0) * 2 + t];
    p11 = &b[(r1 + x1) * 2 + t];
    w00 = lw * (1.0f - fx) * (1.0f - fy);
    w01 = lw * fx * (1.0f - fy);
    w10 = lw * (1.0f - fx) * fy;
    w11 = lw * fx * fy;
}

__global__ void k_sample(const float* __restrict__ uv,
                         const float* __restrict__ p,
                         float* __restrict__ out, int N) {
    int idx = blockIdx.x * blockDim.x + threadIdx.x;
    int q = idx >> 1;
    if (q >= N) return;
    int t = idx & 1;

    float2 uvq = __ldg(reinterpret_cast<const float2*>(uv) + q);
    float  pp  = __ldg(&p[q]);

    float lf = pp * (float)(NLEV - 1);
    int   l0 = min((int)lf, NLEV - 1);          // pp >= 0 -> trunc == floor
    int   l1 = min(l0 + 1, NLEV - 1);
    float alpha = lf - (float)l0;

    float gx = 2.0f * uvq.x - 1.0f;
    float gy = 2.0f * uvq.y - 1.0f;

    const uint4 *a00, *a01, *a10, *a11, *b00, *b01, *b10, *b11;
    float wa00, wa01, wa10, wa11, wb00, wb01, wb10, wb11;
    lvl_setup(l0, gx, gy, t, 1.0f - alpha, a00, a01, a10, a11, wa00, wa01, wa10, wa11);
    lvl_setup(l1, gx, gy, t, alpha,        b00, b01, b10, b11, wb00, wb01, wb10, wb11);

    // batch all 8 texel loads
    uint4 va0 = __ldg(a00);
    uint4 va1 = __ldg(a01);
    uint4 va2 = __ldg(a10);
    uint4 va3 = __ldg(a11);
    uint4 vb0 = __ldg(b00);
    uint4 vb1 = __ldg(b01);
    uint4 vb2 = __ldg(b10);
    uint4 vb3 = __ldg(b11);

    float4 A = make_float4(0.f, 0.f, 0.f, 0.f);
    float4 B = make_float4(0.f, 0.f, 0.f, 0.f);
#define ACC(V, W) {                                                  \
        float2 f0 = u2f2(V.x); A.x += (W) * f0.x; A.y += (W) * f0.y;  \
        float2 f1 = u2f2(V.y); A.z += (W) * f1.x; A.w += (W) * f1.y;  \
        float2 f2 = u2f2(V.z); B.x += (W) * f2.x; B.y += (W) * f2.y;  \
        float2 f3 = u2f2(V.w); B.z += (W) * f3.x; B.w += (W) * f3.y; }
    ACC(va0, wa00) ACC(va1, wa01) ACC(va2, wa10) ACC(va3, wa11)
    ACC(vb0, wb00) ACC(vb1, wb01) ACC(vb2, wb10) ACC(vb3, wb11)
#undef ACC

    // streaming stores: keep the 64MB output from evicting the pyramid in L2
    float4* o = reinterpret_cast<float4*>(out) + q * 4 + t * 2;
    __stcs(o,     A);
    __stcs(o + 1, B);
}

// ---------------------------------------------------------------------------
extern "C" void kernel_launch(void* const* d_in, const int* in_sizes, int n_in,
                              void* d_out, int out_size) {
    const float* uv  = (const float*)d_in[0];
    const float* p   = (const float*)d_in[1];
    const float* tex = (const float*)d_in[2];
    float* out = (float*)d_out;
    int N = in_sizes[1];          // number of queries (p element count)

    k_transpose<<<65536 / 128, 128>>>(tex);
    k_mips<<<(2 * 87376 + 255) / 256, 256>>>();
    int total = N * 2;
    k_sample<<<(total + 255) / 256, 256>>>(uv, p, out, N);
}

// round 7
// speedup vs baseline: 1.0468x; 1.0468x over previous
#include <cuda_runtime.h>
#include <cuda_fp16.h>

// ---------------------------------------------------------------------------
// Mipmapped texture sampling, GB300 — fp16 pyramid (32B/texel, HWC).
// Level i (i>=1) texel = 0.25 * 2x2 of base at y0 = y*2^i + 2^(i-1) - 1
// (exact algebra of align_corners=False bilinear downsample by 2^i).
// NO addressable local state escapes to memory: arrays only with
// fully-unrolled constant indices, scalar bitcasts only.
// ---------------------------------------------------------------------------

#define NLEV 8

__device__ __align__(16) __half g_pyr[5592320];

__constant__ int c_off[NLEV] = {
    0, 4194304, 5242880, 5505024, 5570560, 5586944, 5591040, 5592064
};

__device__ __forceinline__ float2 u2f2(unsigned u) {
    return __half22float2(*reinterpret_cast<const __half2*>(&u));
}
__device__ __forceinline__ unsigned f2u(float a, float b) {
    __half2 h = __floats2half2_rn(a, b);
    return *reinterpret_cast<const unsigned*>(&h);
}
__device__ __forceinline__ float f4get(const float4& v, int j) {
    // j is compile-time constant after full unroll
    return j == 0 ? v.x : (j == 1 ? v.y : (j == 2 ? v.z : v.w));
}

// ---------------------------------------------------------------------------
// Kernel 1: CHW (16,512,512) fp32 -> HWC fp16 level 0.
// 2 threads per 4-pixel group (131,072 threads): each thread does
// 8 x LDG.128 (one per plane, 128B in flight) and 4 x STG.128.
// t = idx & 1 -> adjacent threads write adjacent 16B: stores fully coalesced.
// ---------------------------------------------------------------------------
__global__ void k_transpose(const float* __restrict__ tex) {
    int idx = blockIdx.x * blockDim.x + threadIdx.x;   // 131072 threads
    if (idx >= 131072) return;
    int t   = idx & 1;        // 0: channels 0-7, 1: channels 8-15
    int grp = idx >> 1;       // 4-pixel group
    const int plane4 = 512 * 512 / 4;
    const float4* src = reinterpret_cast<const float4*>(tex) + (8 * t) * plane4 + grp;

    float4 v0 = __ldg(src);
    float4 v1 = __ldg(src + plane4);
    float4 v2 = __ldg(src + 2 * plane4);
    float4 v3 = __ldg(src + 3 * plane4);
    float4 v4 = __ldg(src + 4 * plane4);
    float4 v5 = __ldg(src + 5 * plane4);
    float4 v6 = __ldg(src + 6 * plane4);
    float4 v7 = __ldg(src + 7 * plane4);

    uint4* dst = reinterpret_cast<uint4*>(g_pyr) + grp * 8 + t;  // 4 texels * 2 uint4
#pragma unroll
    for (int j = 0; j < 4; j++) {
        uint4 a;
        a.x = f2u(f4get(v0, j), f4get(v1, j));
        a.y = f2u(f4get(v2, j), f4get(v3, j));
        a.z = f2u(f4get(v4, j), f4get(v5, j));
        a.w = f2u(f4get(v6, j), f4get(v7, j));
        dst[2 * j] = a;
    }
}

// ---------------------------------------------------------------------------
// Kernel 2: levels 1..7 as direct 2x2 average of level 0.
// 2 threads per destination texel (8 channels each), register accumulators.
// ---------------------------------------------------------------------------
__global__ void k_mips() {
    int idx = blockIdx.x * blockDim.x + threadIdx.x;
    if (idx >= 2 * 87376) return;
    int t   = idx & 1;
    int rem = idx >> 1;

    int l = 1;
#pragma unroll
    for (int i = 1; i < NLEV; i++) {
        int np = (512 >> i) * (512 >> i);
        if (rem < np) { l = i; break; }
        rem -= np;
    }
    int s  = 512 >> l;
    int x  = rem & (s - 1);
    int y  = rem >> (9 - l);
    int sc = 1 << l;
    int x0 = x * sc + (sc >> 1) - 1;
    int y0 = y * sc + (sc >> 1) - 1;

    const uint4* base = reinterpret_cast<const uint4*>(g_pyr);
    uint4 va = __ldg(&base[(y0       * 512 + x0    ) * 2 + t]);
    uint4 vb = __ldg(&base[(y0       * 512 + x0 + 1) * 2 + t]);
    uint4 vc = __ldg(&base[((y0 + 1) * 512 + x0    ) * 2 + t]);
    uint4 vd = __ldg(&base[((y0 + 1) * 512 + x0 + 1) * 2 + t]);

    float4 A = make_float4(0.f, 0.f, 0.f, 0.f);
    float4 B = make_float4(0.f, 0.f, 0.f, 0.f);
#define ACC(V) {                                               \
        float2 f0 = u2f2(V.x); A.x += f0.x; A.y += f0.y;        \
        float2 f1 = u2f2(V.y); A.z += f1.x; A.w += f1.y;        \
        float2 f2 = u2f2(V.z); B.x += f2.x; B.y += f2.y;        \
        float2 f3 = u2f2(V.w); B.z += f3.x; B.w += f3.y; }
    ACC(va) ACC(vb) ACC(vc) ACC(vd)
#undef ACC

    uint4 r;
    r.x = f2u(0.25f * A.x, 0.25f * A.y);
    r.y = f2u(0.25f * A.z, 0.25f * A.w);
    r.z = f2u(0.25f * B.x, 0.25f * B.y);
    r.w = f2u(0.25f * B.z, 0.25f * B.w);
    reinterpret_cast<uint4*>(g_pyr + c_off[l])[(y * s + x) * 2 + t] = r;
}

// ---------------------------------------------------------------------------
// Kernel 3: sample. 2 threads/query, 8 channels each (one LDG.128 per texel).
// All 8 loads (both levels) issued before any accumulation (MLP=8).
// ---------------------------------------------------------------------------
__device__ __forceinline__ void lvl_setup(int l, float gx, float gy, int t, float lw,
        const uint4*& p00, const uint4*& p01, const uint4*& p10, const uint4*& p11,
        float& w00, float& w01, float& w10, float& w11) {
    int   s  = 512 >> l;
    float fs = (float)(s - 1);
    float x = fminf(fmaxf((gx + 1.0f) * 0.5f * fs, 0.0f), fs);
    float y = fminf(fmaxf((gy + 1.0f) * 0.5f * fs, 0.0f), fs);
    int x0 = (int)x;
    int y0 = (int)y;
    int x1 = min(x0 + 1, s - 1);
    int y1 = min(y0 + 1, s - 1);
    float fx = x - (float)x0;
    float fy = y - (float)y0;

    const uint4* b = reinterpret_cast<const uint4*>(g_pyr + c_off[l]);
    int r0 = y0 * s, r1 = y1 * s;
    p00 = &b[(r0 + x0) * 2 + t];
    p01 = &b[(r0 + x1) * 2 + t];
    p10 = &b[(r1 + x0) * 2 + t];
    p11 = &b[(r1 + x1) * 2 + t];
    w00 = lw * (1.0f - fx) * (1.0f - fy);
    w01 = lw * fx * (1.0f - fy);
    w10 = lw * (1.0f - fx) * fy;
    w11 = lw * fx * fy;
}

__global__ void k_sample(const float* __restrict__ uv,
                         const float* __restrict__ p,
                         float* __restrict__ out, int N) {
    int idx = blockIdx.x * blockDim.x + threadIdx.x;
    int q = idx >> 1;
    if (q >= N) return;
    int t = idx & 1;

    float2 uvq = __ldg(reinterpret_cast<const float2*>(uv) + q);
    float  pp  = __ldg(&p[q]);

    float lf = pp * (float)(NLEV - 1);
    int   l0 = min((int)lf, NLEV - 1);          // pp >= 0 -> trunc == floor
    int   l1 = min(l0 + 1, NLEV - 1);
    float alpha = lf - (float)l0;

    float gx = 2.0f * uvq.x - 1.0f;
    float gy = 2.0f * uvq.y - 1.0f;

    const uint4 *a00, *a01, *a10, *a11, *b00, *b01, *b10, *b11;
    float wa00, wa01, wa10, wa11, wb00, wb01, wb10, wb11;
    lvl_setup(l0, gx, gy, t, 1.0f - alpha, a00, a01, a10, a11, wa00, wa01, wa10, wa11);
    lvl_setup(l1, gx, gy, t, alpha,        b00, b01, b10, b11, wb00, wb01, wb10, wb11);

    // batch all 8 texel loads
    uint4 va0 = __ldg(a00);
    uint4 va1 = __ldg(a01);
    uint4 va2 = __ldg(a10);
    uint4 va3 = __ldg(a11);
    uint4 vb0 = __ldg(b00);
    uint4 vb1 = __ldg(b01);
    uint4 vb2 = __ldg(b10);
    uint4 vb3 = __ldg(b11);

    float4 A = make_float4(0.f, 0.f, 0.f, 0.f);
    float4 B = make_float4(0.f, 0.f, 0.f, 0.f);
#define ACC(V, W) {                                                  \
        float2 f0 = u2f2(V.x); A.x += (W) * f0.x; A.y += (W) * f0.y;  \
        float2 f1 = u2f2(V.y); A.z += (W) * f1.x; A.w += (W) * f1.y;  \
        float2 f2 = u2f2(V.z); B.x += (W) * f2.x; B.y += (W) * f2.y;  \
        float2 f3 = u2f2(V.w); B.z += (W) * f3.x; B.w += (W) * f3.y; }
    ACC(va0, wa00) ACC(va1, wa01) ACC(va2, wa10) ACC(va3, wa11)
    ACC(vb0, wb00) ACC(vb1, wb01) ACC(vb2, wb10) ACC(vb3, wb11)
#undef ACC

    // streaming stores: keep the 64MB output from evicting the pyramid in L2
    float4* o = reinterpret_cast<float4*>(out) + q * 4 + t * 2;
    __stcs(o,     A);
    __stcs(o + 1, B);
}

// ---------------------------------------------------------------------------
extern "C" void kernel_launch(void* const* d_in, const int* in_sizes, int n_in,
                              void* d_out, int out_size) {
    const float* uv  = (const float*)d_in[0];
    const float* p   = (const float*)d_in[1];
    const float* tex = (const float*)d_in[2];
    float* out = (float*)d_out;
    int N = in_sizes[1];          // number of queries (p element count)

    k_transpose<<<131072 / 256, 256>>>(tex);
    k_mips<<<(2 * 87376 + 255) / 256, 256>>>();
    int total = N * 2;
    k_sample<<<(total + 255) / 256, 256>>>(uv, p, out, N);
}